// round 8
// baseline (speedup 1.0000x reference)
#include <cuda_runtime.h>

// out[to_i[j]] = mat_i[from_i[j]], 3 segments of L rows, D=64 fp32 (256B/row).
// 16 threads per row (one float4 each), U=6 rows/thread with compile-time
// segment mapping (rows {r0, r0+L/2} of each segment): 12 coalesced index
// loads, 6 independent LDG.128 gathers (MLP=6), 6 STG.128 scatters.
//
// R6 change: scatter stores use evict-first policy (st.global.cs) — output is
// written once and never re-read, so keeping it out of L2 preserves residency
// for the gather side, which has ~2.4x average reuse per source row
// (1.2M reads over 1.5M source rows). Index loads use ld.global.cs (read-once).

#define D4 16   // D=64 floats = 16 float4

__device__ __forceinline__ void stcs4(float4* p, float4 v) {
    asm volatile("st.global.cs.v4.f32 [%0], {%1, %2, %3, %4};"
                 :: "l"(p), "f"(v.x), "f"(v.y), "f"(v.z), "f"(v.w) : "memory");
}
__device__ __forceinline__ int ldcs_i(const int* p) {
    int v;
    asm volatile("ld.global.cs.s32 %0, [%1];" : "=r"(v) : "l"(p));
    return v;
}

__global__ void __launch_bounds__(256)
mis_u6_kernel(const float4* __restrict__ m0,
              const float4* __restrict__ m1,
              const float4* __restrict__ m2,
              const int*    __restrict__ f0,
              const int*    __restrict__ f1,
              const int*    __restrict__ f2,
              const int*    __restrict__ t0,
              const int*    __restrict__ t1,
              const int*    __restrict__ t2,
              float4*       __restrict__ out,
              int halfL)
{
    const int tid = blockIdx.x * blockDim.x + threadIdx.x;
    const int q   = tid & (D4 - 1);
    const int r0  = tid >> 4;                 // [0, halfL)
    if (r0 >= halfL) return;
    const int r1  = r0 + halfL;

    // Phase 1: all 12 index loads (coalesced / warp-broadcast), read-once.
    const int s0 = ldcs_i(f0 + r0), d0 = ldcs_i(t0 + r0);
    const int s1 = ldcs_i(f0 + r1), d1 = ldcs_i(t0 + r1);
    const int s2 = ldcs_i(f1 + r0), d2 = ldcs_i(t1 + r0);
    const int s3 = ldcs_i(f1 + r1), d3 = ldcs_i(t1 + r1);
    const int s4 = ldcs_i(f2 + r0), d4 = ldcs_i(t2 + r0);
    const int s5 = ldcs_i(f2 + r1), d5 = ldcs_i(t2 + r1);

    // Phase 2: 6 independent 16B gathers in flight (default caching: the
    // gather stream has ~2.4x reuse and should occupy L2).
    float4 v0 = __ldg(m0 + (size_t)s0 * D4 + q);
    float4 v1 = __ldg(m0 + (size_t)s1 * D4 + q);
    float4 v2 = __ldg(m1 + (size_t)s2 * D4 + q);
    float4 v3 = __ldg(m1 + (size_t)s3 * D4 + q);
    float4 v4 = __ldg(m2 + (size_t)s4 * D4 + q);
    float4 v5 = __ldg(m2 + (size_t)s5 * D4 + q);

    // Phase 3: scatters, evict-first (write-once data must not displace the
    // gather-resident L2 set).
    stcs4(out + (size_t)d0 * D4 + q, v0);
    stcs4(out + (size_t)d1 * D4 + q, v1);
    stcs4(out + (size_t)d2 * D4 + q, v2);
    stcs4(out + (size_t)d3 * D4 + q, v3);
    stcs4(out + (size_t)d4 * D4 + q, v4);
    stcs4(out + (size_t)d5 * D4 + q, v5);
}

// Generic fallback (used only if L is odd): one thread per row-float4.
__global__ void __launch_bounds__(256)
mis_generic_kernel(const float4* __restrict__ m0,
                   const float4* __restrict__ m1,
                   const float4* __restrict__ m2,
                   const int*    __restrict__ f0,
                   const int*    __restrict__ f1,
                   const int*    __restrict__ f2,
                   const int*    __restrict__ t0,
                   const int*    __restrict__ t1,
                   const int*    __restrict__ t2,
                   float4*       __restrict__ out,
                   int L)
{
    int tid = blockIdx.x * blockDim.x + threadIdx.x;
    int row = tid >> 4;
    int q   = tid & (D4 - 1);
    if (row >= 3 * L) return;
    const float4* m; const int* f; const int* t; int r;
    if (row < L)          { m = m0; f = f0; t = t0; r = row;         }
    else if (row < 2 * L) { m = m1; f = f1; t = t1; r = row - L;     }
    else                  { m = m2; f = f2; t = t2; r = row - 2 * L; }
    int src = __ldg(f + r);
    int dst = __ldg(t + r);
    out[(size_t)dst * D4 + q] = __ldg(m + (size_t)src * D4 + q);
}

extern "C" void kernel_launch(void* const* d_in, const int* in_sizes, int n_in,
                              void* d_out, int out_size)
{
    const float4* m0 = (const float4*)d_in[0];
    const float4* m1 = (const float4*)d_in[1];
    const float4* m2 = (const float4*)d_in[2];
    const int*    f0 = (const int*)d_in[3];
    const int*    f1 = (const int*)d_in[4];
    const int*    f2 = (const int*)d_in[5];
    const int*    t0 = (const int*)d_in[6];
    const int*    t1 = (const int*)d_in[7];
    const int*    t2 = (const int*)d_in[8];
    float4* out = (float4*)d_out;

    const int L     = in_sizes[3];     // length of from0
    const int block = 256;

    if ((L & 1) == 0) {
        const int halfL = L >> 1;
        const long long threads = (long long)halfL * D4;
        const int grid = (int)((threads + block - 1) / block);
        mis_u6_kernel<<<grid, block>>>(m0, m1, m2, f0, f1, f2,
                                       t0, t1, t2, out, halfL);
    } else {
        const long long threads = (long long)3 * L * D4;
        const int grid = (int)((threads + block - 1) / block);
        mis_generic_kernel<<<grid, block>>>(m0, m1, m2, f0, f1, f2,
                                            t0, t1, t2, out, L);
    }
}